// round 15
// baseline (speedup 1.0000x reference)
#include <cuda_runtime.h>
#include <cuda_fp16.h>
#include <cstdint>

using hf = __half;

#define BSZ   8
#define NSEQ  1024
#define EMB   768
#define NH    12
#define DH    64
#define MTOK  8192
#define LOG2E 1.4426950408889634f
#define MSHIFT 16.0f

// GEMM tiling: 128x128x32, 8 warps, warp tile 64x32, pure fp16, 3-stage
#define BM 128
#define BN 128
#define BK 32
#define KSG 40
#define NKT (EMB / BK)     // 24

#define G_AHI   0
#define G_BHI   10240
#define G_STAGE 20480           // A(10240) + B(10240)
#define G_SMEM  (3 * G_STAGE)   // 61440

// Attention: CTA = 64 q / 4 warps, kv tile 32, K/V 2-stage, bias 3-buffer depth-2
#define KKS 72      // K row stride (halves)
#define VKS 40      // V row stride (halves)
#define BSP 36      // bias row stride (floats)
#define A_KHI    0
#define A_VHI    4608
#define A_KVSTG  9728                     // one K/V stage
#define A_BIAS   (2 * A_KVSTG)            // 19456
#define A_BB     9216                     // one bias buffer (64*36*4)
#define A_SMEM   (A_BIAS + 3 * A_BB)      // 47104
#define NTILES   (NSEQ / 32)              // 32

// ---------------------------------------------------------------------------
// Scratch (device globals: allocation-free rule)
// ---------------------------------------------------------------------------
__device__ hf g_xhi[(size_t)MTOK * EMB];
__device__ hf g_whi[4][(size_t)EMB * EMB];
__device__ hf g_qhi[(size_t)BSZ * NH * NSEQ * DH];       // (b,h,n,d)
__device__ hf g_khi[(size_t)BSZ * NH * NSEQ * DH];       // (b,h,n,d)
__device__ hf g_vhi[(size_t)BSZ * NH * DH * NSEQ];       // (b,h,d,n)
__device__ hf g_ahi[(size_t)MTOK * EMB];                 // (b,n,e)

// ---------------------------------------------------------------------------
// primitives
// ---------------------------------------------------------------------------
__device__ __forceinline__ void mma16816(float c[4],
                                         uint32_t a0, uint32_t a1, uint32_t a2, uint32_t a3,
                                         uint32_t b0, uint32_t b1)
{
    asm volatile(
        "mma.sync.aligned.m16n8k16.row.col.f32.f16.f16.f32 "
        "{%0,%1,%2,%3}, {%4,%5,%6,%7}, {%8,%9}, {%0,%1,%2,%3};\n"
        : "+f"(c[0]), "+f"(c[1]), "+f"(c[2]), "+f"(c[3])
        : "r"(a0), "r"(a1), "r"(a2), "r"(a3), "r"(b0), "r"(b1));
}

__device__ __forceinline__ void ldsm4(uint32_t& r0, uint32_t& r1, uint32_t& r2, uint32_t& r3,
                                      uint32_t addr)
{
    asm volatile("ldmatrix.sync.aligned.m8n8.x4.shared.b16 {%0,%1,%2,%3}, [%4];"
                 : "=r"(r0), "=r"(r1), "=r"(r2), "=r"(r3) : "r"(addr));
}

__device__ __forceinline__ uint32_t pk2h(float x, float y)
{
    __half2 h = __floats2half2_rn(x, y);
    return *reinterpret_cast<uint32_t*>(&h);
}

__device__ __forceinline__ float fexp2(float x)
{
    float r;
    asm("ex2.approx.f32 %0, %1;" : "=f"(r) : "f"(x));
    return r;
}

__device__ __forceinline__ uint32_t smem_u32(const void* p)
{
    return (uint32_t)__cvta_generic_to_shared(p);
}

__device__ __forceinline__ void cpa16(uint32_t dst, const void* src)
{
    asm volatile("cp.async.cg.shared.global [%0], [%1], 16;" :: "r"(dst), "l"(src));
}
__device__ __forceinline__ void cpa_commit() { asm volatile("cp.async.commit_group;"); }
template <int N>
__device__ __forceinline__ void cpa_wait() { asm volatile("cp.async.wait_group %0;" :: "n"(N)); }

// ---------------------------------------------------------------------------
// conversion kernels
// ---------------------------------------------------------------------------
__global__ void conv_x(const float* __restrict__ src)
{
    int i = (blockIdx.x * blockDim.x + threadIdx.x) * 2;
    if (i >= MTOK * EMB) return;
    float2 v = *(const float2*)(src + i);
    *(uint32_t*)&g_xhi[i] = pk2h(v.x, v.y);
}

__global__ void conv_w4(const float* __restrict__ Wq, const float* __restrict__ Wk,
                        const float* __restrict__ Wv, const float* __restrict__ Wo)
{
    const int z = blockIdx.y;
    const float* src = (z == 0) ? Wq : (z == 1) ? Wk : (z == 2) ? Wv : Wo;
    int i = (blockIdx.x * blockDim.x + threadIdx.x) * 2;
    if (i >= EMB * EMB) return;
    float2 v = *(const float2*)(src + i);
    *(uint32_t*)&g_whi[z][i] = pk2h(v.x, v.y);
}

// ---------------------------------------------------------------------------
// GEMM core: acc[4][4][4] += Xhi[row0:+128,:] * Whi[col0:+128,:]^T  (pure fp16)
// 256 threads / 8 warps, warp tile 64x32, 3-stage cp.async.
// ---------------------------------------------------------------------------
__device__ __forceinline__ void gemm_prefetch(char* sm, int stg,
    const hf* __restrict__ Xhi, const hf* __restrict__ Whi,
    int row0, int col0, int kt, int tid)
{
    char* base = sm + stg * G_STAGE;
    const int r = tid >> 2, c = (tid & 3) * 8;
    const uint32_t so  = (uint32_t)(r * KSG + c) * 2;
    const uint32_t so2 = so + 64 * KSG * 2;
    const size_t ga1 = (size_t)(row0 + r) * EMB + kt + c;
    const size_t ga2 = ga1 + (size_t)64 * EMB;
    cpa16(smem_u32(base + G_AHI) + so,  Xhi + ga1);
    cpa16(smem_u32(base + G_AHI) + so2, Xhi + ga2);
    const size_t gb1 = (size_t)(col0 + r) * EMB + kt + c;
    const size_t gb2 = gb1 + (size_t)64 * EMB;
    cpa16(smem_u32(base + G_BHI) + so,  Whi + gb1);
    cpa16(smem_u32(base + G_BHI) + so2, Whi + gb2);
}

__device__ __forceinline__ void gemm_core(char* sm,
    const hf* __restrict__ Xhi, const hf* __restrict__ Whi,
    int row0, int col0, float acc[4][4][4])
{
    const int tid = threadIdx.x, lane = tid & 31, wid = tid >> 5;
    const int wm = (wid & 1) * 64, wn = (wid >> 1) * 32;
    const int lrow = lane & 15, lc8 = (lane >> 4) * 8;

    const uint32_t oA = (uint32_t)((wm + lrow) * KSG + lc8) * 2;
    const uint32_t oB = (uint32_t)((wn + lrow) * KSG + lc8) * 2;
    const uint32_t smb = smem_u32(sm);

    gemm_prefetch(sm, 0, Xhi, Whi, row0, col0, 0, tid);
    cpa_commit();
    gemm_prefetch(sm, 1, Xhi, Whi, row0, col0, BK, tid);
    cpa_commit();

    int stg = 0;
    for (int t = 0; t < NKT; t++) {
        if (t + 2 < NKT) cpa_wait<1>(); else cpa_wait<0>();
        __syncthreads();
        if (t + 2 < NKT) {
            int ps = stg + 2; if (ps >= 3) ps -= 3;
            gemm_prefetch(sm, ps, Xhi, Whi, row0, col0, (t + 2) * BK, tid);
            cpa_commit();
        }
        const uint32_t sb = smb + (uint32_t)stg * G_STAGE;
        const uint32_t aAh = sb + G_AHI + oA;
        const uint32_t aBh = sb + G_BHI + oB;

        #pragma unroll
        for (int kk = 0; kk < 2; kk++) {
            const uint32_t ko = kk * 32;
            uint32_t Ah[4][4];
            #pragma unroll
            for (int mt = 0; mt < 4; mt++)
                ldsm4(Ah[mt][0], Ah[mt][1], Ah[mt][2], Ah[mt][3], aAh + ko + mt * 16 * KSG * 2);
            #pragma unroll
            for (int p = 0; p < 2; p++) {
                uint32_t h0, h1, h2, h3;
                ldsm4(h0, h1, h2, h3, aBh + ko + p * 16 * KSG * 2);
                #pragma unroll
                for (int mt = 0; mt < 4; mt++) {
                    mma16816(acc[mt][2*p],   Ah[mt][0],Ah[mt][1],Ah[mt][2],Ah[mt][3], h0, h2);
                    mma16816(acc[mt][2*p+1], Ah[mt][0],Ah[mt][1],Ah[mt][2],Ah[mt][3], h1, h3);
                }
            }
        }
        stg = (stg + 1 == 3) ? 0 : stg + 1;
    }
}

// ---------------------------------------------------------------------------
// QKV projection: pure fp16 GEMM. Q pre-scaled by d^-0.5 * log2(e).
// ---------------------------------------------------------------------------
__global__ __launch_bounds__(256, 2) void qkv_gemm(
    const float* __restrict__ bq, const float* __restrict__ bk, const float* __restrict__ bv)
{
    extern __shared__ char sm[];
    const int z = blockIdx.z;
    const hf* Whi = g_whi[z];
    const float* bias = (z == 0) ? bq : (z == 1) ? bk : bv;
    const float scale = (z == 0) ? 0.125f * LOG2E : 1.0f;

    const int row0 = blockIdx.y * BM, col0 = blockIdx.x * BN;
    float acc[4][4][4] = {};
    gemm_core(sm, g_xhi, Whi, row0, col0, acc);

    const int lane = threadIdx.x & 31, wid = threadIdx.x >> 5;
    const int wm = (wid & 1) * 64, wn = (wid >> 1) * 32;
    const int g = lane >> 2, tg = lane & 3;

    #pragma unroll
    for (int mt = 0; mt < 4; mt++) {
        #pragma unroll
        for (int nt = 0; nt < 4; nt++) {
            const int c0 = col0 + wn + nt * 8 + tg * 2;
            const int h = c0 >> 6, d0 = c0 & 63;
            const float b0f = bias[c0], b1f = bias[c0 + 1];
            #pragma unroll
            for (int r = 0; r < 2; r++) {
                const int m = row0 + wm + mt * 16 + g + r * 8;
                const int b = m >> 10, n = m & 1023;
                float v0 = (acc[mt][nt][r * 2 + 0] + b0f) * scale;
                float v1 = (acc[mt][nt][r * 2 + 1] + b1f) * scale;
                if (z == 0) {
                    size_t base = ((size_t)(b * NH + h) * NSEQ + n) * DH + d0;
                    *(uint32_t*)&g_qhi[base] = pk2h(v0, v1);
                } else if (z == 1) {
                    size_t base = ((size_t)(b * NH + h) * NSEQ + n) * DH + d0;
                    *(uint32_t*)&g_khi[base] = pk2h(v0, v1);
                } else {
                    size_t vb = ((size_t)(b * NH + h) * DH + d0) * NSEQ + n;
                    g_vhi[vb]        = __float2half_rn(v0);
                    g_vhi[vb + NSEQ] = __float2half_rn(v1);
                }
            }
        }
    }
}

// ---------------------------------------------------------------------------
// Output projection: pure fp16 GEMM
// ---------------------------------------------------------------------------
__global__ __launch_bounds__(256, 2) void out_gemm(const float* __restrict__ bias,
                                                   float* __restrict__ out)
{
    extern __shared__ char sm[];
    const int row0 = blockIdx.y * BM, col0 = blockIdx.x * BN;
    float acc[4][4][4] = {};
    gemm_core(sm, g_ahi, g_whi[3], row0, col0, acc);

    const int lane = threadIdx.x & 31, wid = threadIdx.x >> 5;
    const int wm = (wid & 1) * 64, wn = (wid >> 1) * 32;
    const int g = lane >> 2, tg = lane & 3;

    #pragma unroll
    for (int mt = 0; mt < 4; mt++) {
        #pragma unroll
        for (int nt = 0; nt < 4; nt++) {
            const int c0 = col0 + wn + nt * 8 + tg * 2;
            const float b0f = bias[c0], b1f = bias[c0 + 1];
            #pragma unroll
            for (int r = 0; r < 2; r++) {
                const int m = row0 + wm + mt * 16 + g + r * 8;
                float2 v;
                v.x = acc[mt][nt][r * 2 + 0] + b0f;
                v.y = acc[mt][nt][r * 2 + 1] + b1f;
                *(float2*)(out + (size_t)m * EMB + c0) = v;
            }
        }
    }
}

// ---------------------------------------------------------------------------
// Tensor-core flash attention, fixed-shift softmax, all-hi fp16.
// CTA = 64 queries x one (b,h), 128 thr / 4 warps, kv tile 32, 4 CTAs/SM.
// K/V: 2-stage cp.async. Bias: 3-buffer cp.async pipelined 2 TILES AHEAD
// (two commit-groups per iteration + wait_group<1> keeps bias loads
// continuously in flight -> raises DRAM duty cycle).
// ---------------------------------------------------------------------------
__global__ __launch_bounds__(128, 4) void attn_kernel(const float* __restrict__ bias)
{
    extern __shared__ char sm[];
    const int qb = blockIdx.x, bh = blockIdx.y;
    const int tid = threadIdx.x, lane = tid & 31, w = tid >> 5;
    const int g = lane >> 2, tg = lane & 3;
    const int wm = w * 16;
    const int qrow0 = qb * 64;

    // Q fragments, hi only (persistent in registers)
    uint32_t qh[4][4];
    {
        const hf* qbh = g_qhi + ((size_t)bh * NSEQ + qrow0 + wm) * DH;
        #pragma unroll
        for (int ks = 0; ks < 4; ks++) {
            const int kc = ks * 16 + tg * 2;
            qh[ks][0] = *(const uint32_t*)(qbh + g * DH + kc);
            qh[ks][1] = *(const uint32_t*)(qbh + (g + 8) * DH + kc);
            qh[ks][2] = *(const uint32_t*)(qbh + g * DH + kc + 8);
            qh[ks][3] = *(const uint32_t*)(qbh + (g + 8) * DH + kc + 8);
        }
    }

    float o[8][4] = {};
    float l0 = 0.0f, l1 = 0.0f;

    const hf* kph = g_khi + (size_t)bh * NSEQ * DH;
    const hf* vph = g_vhi + (size_t)bh * DH * NSEQ;
    const float* bgm = bias + ((size_t)bh * NSEQ + qrow0) * NSEQ;

    const int lrow = lane & 15, lc8 = (lane >> 4) * 8;
    const uint32_t smb = smem_u32(sm);
    const uint32_t oKm = (uint32_t)(lrow * KKS + lc8) * 2;
    const uint32_t oVm = (uint32_t)(lrow * VKS + lc8) * 2;

    auto prefetch_kv = [&](int t, int buf) {
        char* base = sm + buf * A_KVSTG;
        const int kv0 = t * 32;
        {
            const int r = tid >> 3, c = (tid & 7) * 8;
            #pragma unroll
            for (int ch = 0; ch < 2; ch++) {
                const int row = r + ch * 16;
                cpa16(smem_u32(base + A_KHI) + (uint32_t)(row * KKS + c) * 2,
                      kph + (size_t)(kv0 + row) * DH + c);
            }
        }
        {
            const int r = tid >> 2, c = (tid & 3) * 8;
            #pragma unroll
            for (int ch = 0; ch < 2; ch++) {
                const int row = r + ch * 32;
                cpa16(smem_u32(base + A_VHI) + (uint32_t)(row * VKS + c) * 2,
                      vph + (size_t)row * NSEQ + kv0 + c);
            }
        }
    };

    auto prefetch_bias = [&](int t, int buf) {
        char* base = sm + A_BIAS + buf * A_BB;
        const int kv0 = t * 32;
        const int r = tid >> 3, c = (tid & 7) * 4;     // r 0..15, c 0..28
        #pragma unroll
        for (int ch = 0; ch < 4; ch++) {
            const int row = r + ch * 16;
            cpa16(smem_u32(base) + (uint32_t)(row * BSP + c) * 4,
                  bgm + (size_t)row * NSEQ + kv0 + c);
        }
    };

    // prologue: groups [KV0][bias0][bias1]
    prefetch_kv(0, 0);   cpa_commit();
    prefetch_bias(0, 0); cpa_commit();
    prefetch_bias(1, 1); cpa_commit();

    int bbuf = 0;
    for (int t = 0; t < NTILES; t++) {
        cpa_wait<1>();          // completes KV(t) and bias(t); bias(t+1) stays in flight
        __syncthreads();
        if (t + 1 < NTILES) prefetch_kv(t + 1, (t + 1) & 1);
        cpa_commit();
        if (t + 2 < NTILES) {
            int nb = bbuf + 2; if (nb >= 3) nb -= 3;
            prefetch_bias(t + 2, nb);
        }
        cpa_commit();

        const uint32_t sb = smb + (t & 1) * A_KVSTG;
        const uint32_t aKh = sb + A_KHI + oKm;
        const uint32_t aVh = sb + A_VHI + oVm;

        // S init = bias*log2e - MSHIFT (from bias smem buffer)
        float s[4][4];
        const float* Bsm = (const float*)(sm + A_BIAS + bbuf * A_BB);
        const float* br0 = Bsm + (wm + g) * BSP + tg * 2;
        const float* br1 = Bsm + (wm + g + 8) * BSP + tg * 2;
        #pragma unroll
        for (int nt = 0; nt < 4; nt++) {
            float2 t0 = *(const float2*)(br0 + nt * 8);
            float2 t1 = *(const float2*)(br1 + nt * 8);
            s[nt][0] = fmaf(t0.x, LOG2E, -MSHIFT); s[nt][1] = fmaf(t0.y, LOG2E, -MSHIFT);
            s[nt][2] = fmaf(t1.x, LOG2E, -MSHIFT); s[nt][3] = fmaf(t1.y, LOG2E, -MSHIFT);
        }

        // S += Qhi Khi^T
        #pragma unroll
        for (int p = 0; p < 2; p++) {
            #pragma unroll
            for (int ks = 0; ks < 4; ks++) {
                uint32_t h0, h1, h2, h3;
                ldsm4(h0, h1, h2, h3, aKh + p * (16 * KKS * 2) + ks * 32);
                mma16816(s[2*p],   qh[ks][0],qh[ks][1],qh[ks][2],qh[ks][3], h0, h2);
                mma16816(s[2*p+1], qh[ks][0],qh[ks][1],qh[ks][2],qh[ks][3], h1, h3);
            }
        }

        // fixed-shift exp: p = 2^s; accumulate partial l
        #pragma unroll
        for (int nt = 0; nt < 4; nt++) {
            s[nt][0] = fexp2(s[nt][0]); l0 += s[nt][0];
            s[nt][1] = fexp2(s[nt][1]); l0 += s[nt][1];
            s[nt][2] = fexp2(s[nt][2]); l1 += s[nt][2];
            s[nt][3] = fexp2(s[nt][3]); l1 += s[nt][3];
        }

        // pack P (hi only) into PV A-fragments
        uint32_t ph[2][4];
        #pragma unroll
        for (int j = 0; j < 2; j++) {
            ph[j][0] = pk2h(s[2*j][0],   s[2*j][1]);
            ph[j][1] = pk2h(s[2*j][2],   s[2*j][3]);
            ph[j][2] = pk2h(s[2*j+1][0], s[2*j+1][1]);
            ph[j][3] = pk2h(s[2*j+1][2], s[2*j+1][3]);
        }

        // O += Phi Vhi
        #pragma unroll
        for (int p = 0; p < 4; p++) {
            #pragma unroll
            for (int j = 0; j < 2; j++) {
                uint32_t h0, h1, h2, h3;
                ldsm4(h0, h1, h2, h3, aVh + p * (16 * VKS * 2) + j * 32);
                mma16816(o[2*p],   ph[j][0],ph[j][1],ph[j][2],ph[j][3], h0, h2);
                mma16816(o[2*p+1], ph[j][0],ph[j][1],ph[j][2],ph[j][3], h1, h3);
            }
        }

        bbuf = (bbuf + 1 == 3) ? 0 : bbuf + 1;
    }

    // final l reduction across the 4 tg lanes of each row
    l0 += __shfl_xor_sync(0xffffffffu, l0, 1);
    l0 += __shfl_xor_sync(0xffffffffu, l0, 2);
    l1 += __shfl_xor_sync(0xffffffffu, l1, 1);
    l1 += __shfl_xor_sync(0xffffffffu, l1, 2);

    // epilogue: normalize, pack hi-only fp16, store into (b,n,e)
    const float inv0 = 1.0f / l0, inv1 = 1.0f / l1;
    const int b = bh / NH, h = bh % NH;
    const int n0 = qrow0 + wm + g;
    const size_t base0 = ((size_t)b * NSEQ + n0) * EMB + h * DH;
    const size_t base1 = base0 + (size_t)8 * EMB;
    #pragma unroll
    for (int dn = 0; dn < 8; dn++) {
        const int d = dn * 8 + tg * 2;
        *(uint32_t*)&g_ahi[base0 + d] = pk2h(o[dn][0] * inv0, o[dn][1] * inv0);
        *(uint32_t*)&g_ahi[base1 + d] = pk2h(o[dn][2] * inv1, o[dn][3] * inv1);
    }
}

// ---------------------------------------------------------------------------
extern "C" void kernel_launch(void* const* d_in, const int* in_sizes, int n_in,
                              void* d_out, int out_size)
{
    const float* query     = (const float*)d_in[0];
    const float* attn_bias = (const float*)d_in[1];
    const float* Wq = (const float*)d_in[2];
    const float* bq = (const float*)d_in[3];
    const float* Wk = (const float*)d_in[4];
    const float* bk = (const float*)d_in[5];
    const float* Wv = (const float*)d_in[6];
    const float* bv = (const float*)d_in[7];
    const float* Wo = (const float*)d_in[8];
    const float* bo = (const float*)d_in[9];
    float* out = (float*)d_out;

    cudaFuncSetAttribute(qkv_gemm,    cudaFuncAttributeMaxDynamicSharedMemorySize, G_SMEM);
    cudaFuncSetAttribute(out_gemm,    cudaFuncAttributeMaxDynamicSharedMemorySize, G_SMEM);
    cudaFuncSetAttribute(attn_kernel, cudaFuncAttributeMaxDynamicSharedMemorySize, A_SMEM);

    conv_x<<<(MTOK * EMB / 2 + 255) / 256, 256>>>(query);
    dim3 gw((EMB * EMB / 2 + 255) / 256, 4);
    conv_w4<<<gw, 256>>>(Wq, Wk, Wv, Wo);

    dim3 g1(EMB / BN, MTOK / BM, 3);
    qkv_gemm<<<g1, 256, G_SMEM>>>(bq, bk, bv);

    dim3 g2(NSEQ / 64, BSZ * NH);
    attn_kernel<<<g2, 128, A_SMEM>>>(attn_bias);

    dim3 g3(EMB / BN, MTOK / BM);
    out_gemm<<<g3, 256, G_SMEM>>>(bo, out);
}

// round 16
// speedup vs baseline: 1.0273x; 1.0273x over previous
#include <cuda_runtime.h>
#include <cuda_fp16.h>
#include <cstdint>

using hf = __half;

#define BSZ   8
#define NSEQ  1024
#define EMB   768
#define NH    12
#define DH    64
#define MTOK  8192
#define LOG2E 1.4426950408889634f
#define MSHIFT 16.0f

// GEMM tiling: 128x128x32, 8 warps, warp tile 64x32, pure fp16, 4-stage
#define BM 128
#define BN 128
#define BK 32
#define KSG 40
#define NKT (EMB / BK)     // 24

#define G_AHI   0
#define G_BHI   10240
#define G_STAGE 20480           // A(10240) + B(10240)
#define G_SMEM  (4 * G_STAGE)   // 81920

// Attention (R14 config): CTA = 64 q / 4 warps, kv tile 32, K/V 2-stage, bias in regs
#define KKS 72      // K row stride (halves)
#define VKS 40      // V row stride (halves)
#define A_KHI   0
#define A_VHI   4608
#define A_STAGE 9728
#define A_SMEM  (2 * A_STAGE)   // 19456

// ---------------------------------------------------------------------------
// Scratch (device globals: allocation-free rule)
// ---------------------------------------------------------------------------
__device__ hf g_xhi[(size_t)MTOK * EMB];
__device__ hf g_whi[4][(size_t)EMB * EMB];
__device__ hf g_qhi[(size_t)BSZ * NH * NSEQ * DH];       // (b,h,n,d)
__device__ hf g_khi[(size_t)BSZ * NH * NSEQ * DH];       // (b,h,n,d)
__device__ hf g_vhi[(size_t)BSZ * NH * DH * NSEQ];       // (b,h,d,n)
__device__ hf g_ahi[(size_t)MTOK * EMB];                 // (b,n,e)

// ---------------------------------------------------------------------------
// primitives
// ---------------------------------------------------------------------------
__device__ __forceinline__ void mma16816(float c[4],
                                         uint32_t a0, uint32_t a1, uint32_t a2, uint32_t a3,
                                         uint32_t b0, uint32_t b1)
{
    asm volatile(
        "mma.sync.aligned.m16n8k16.row.col.f32.f16.f16.f32 "
        "{%0,%1,%2,%3}, {%4,%5,%6,%7}, {%8,%9}, {%0,%1,%2,%3};\n"
        : "+f"(c[0]), "+f"(c[1]), "+f"(c[2]), "+f"(c[3])
        : "r"(a0), "r"(a1), "r"(a2), "r"(a3), "r"(b0), "r"(b1));
}

__device__ __forceinline__ void ldsm4(uint32_t& r0, uint32_t& r1, uint32_t& r2, uint32_t& r3,
                                      uint32_t addr)
{
    asm volatile("ldmatrix.sync.aligned.m8n8.x4.shared.b16 {%0,%1,%2,%3}, [%4];"
                 : "=r"(r0), "=r"(r1), "=r"(r2), "=r"(r3) : "r"(addr));
}

__device__ __forceinline__ uint32_t pk2h(float x, float y)
{
    __half2 h = __floats2half2_rn(x, y);
    return *reinterpret_cast<uint32_t*>(&h);
}

__device__ __forceinline__ float fexp2(float x)
{
    float r;
    asm("ex2.approx.f32 %0, %1;" : "=f"(r) : "f"(x));
    return r;
}

__device__ __forceinline__ uint32_t smem_u32(const void* p)
{
    return (uint32_t)__cvta_generic_to_shared(p);
}

__device__ __forceinline__ void cpa16(uint32_t dst, const void* src)
{
    asm volatile("cp.async.cg.shared.global [%0], [%1], 16;" :: "r"(dst), "l"(src));
}
__device__ __forceinline__ void cpa_commit() { asm volatile("cp.async.commit_group;"); }
template <int N>
__device__ __forceinline__ void cpa_wait() { asm volatile("cp.async.wait_group %0;" :: "n"(N)); }

// ---------------------------------------------------------------------------
// conversion kernels (8-wide vectorized)
// ---------------------------------------------------------------------------
__global__ void conv_x(const float* __restrict__ src)
{
    size_t i = ((size_t)blockIdx.x * blockDim.x + threadIdx.x) * 8;
    if (i >= (size_t)MTOK * EMB) return;
    float4 a = *(const float4*)(src + i);
    float4 b = *(const float4*)(src + i + 4);
    uint4 o;
    o.x = pk2h(a.x, a.y); o.y = pk2h(a.z, a.w);
    o.z = pk2h(b.x, b.y); o.w = pk2h(b.z, b.w);
    *(uint4*)&g_xhi[i] = o;
}

__global__ void conv_w4(const float* __restrict__ Wq, const float* __restrict__ Wk,
                        const float* __restrict__ Wv, const float* __restrict__ Wo)
{
    const int z = blockIdx.y;
    const float* src = (z == 0) ? Wq : (z == 1) ? Wk : (z == 2) ? Wv : Wo;
    size_t i = ((size_t)blockIdx.x * blockDim.x + threadIdx.x) * 8;
    if (i >= (size_t)EMB * EMB) return;
    float4 a = *(const float4*)(src + i);
    float4 b = *(const float4*)(src + i + 4);
    uint4 o;
    o.x = pk2h(a.x, a.y); o.y = pk2h(a.z, a.w);
    o.z = pk2h(b.x, b.y); o.w = pk2h(b.z, b.w);
    *(uint4*)&g_whi[z][i] = o;
}

// ---------------------------------------------------------------------------
// GEMM core: acc[4][4][4] += Xhi[row0:+128,:] * Whi[col0:+128,:]^T  (pure fp16)
// 256 threads / 8 warps, warp tile 64x32, 4-stage cp.async.
// ---------------------------------------------------------------------------
__device__ __forceinline__ void gemm_prefetch(char* sm, int stg,
    const hf* __restrict__ Xhi, const hf* __restrict__ Whi,
    int row0, int col0, int kt, int tid)
{
    char* base = sm + stg * G_STAGE;
    const int r = tid >> 2, c = (tid & 3) * 8;
    const uint32_t so  = (uint32_t)(r * KSG + c) * 2;
    const uint32_t so2 = so + 64 * KSG * 2;
    const size_t ga1 = (size_t)(row0 + r) * EMB + kt + c;
    const size_t ga2 = ga1 + (size_t)64 * EMB;
    cpa16(smem_u32(base + G_AHI) + so,  Xhi + ga1);
    cpa16(smem_u32(base + G_AHI) + so2, Xhi + ga2);
    const size_t gb1 = (size_t)(col0 + r) * EMB + kt + c;
    const size_t gb2 = gb1 + (size_t)64 * EMB;
    cpa16(smem_u32(base + G_BHI) + so,  Whi + gb1);
    cpa16(smem_u32(base + G_BHI) + so2, Whi + gb2);
}

__device__ __forceinline__ void gemm_core(char* sm,
    const hf* __restrict__ Xhi, const hf* __restrict__ Whi,
    int row0, int col0, float acc[4][4][4])
{
    const int tid = threadIdx.x, lane = tid & 31, wid = tid >> 5;
    const int wm = (wid & 1) * 64, wn = (wid >> 1) * 32;
    const int lrow = lane & 15, lc8 = (lane >> 4) * 8;

    const uint32_t oA = (uint32_t)((wm + lrow) * KSG + lc8) * 2;
    const uint32_t oB = (uint32_t)((wn + lrow) * KSG + lc8) * 2;
    const uint32_t smb = smem_u32(sm);

    gemm_prefetch(sm, 0, Xhi, Whi, row0, col0, 0, tid);
    cpa_commit();
    gemm_prefetch(sm, 1, Xhi, Whi, row0, col0, BK, tid);
    cpa_commit();
    gemm_prefetch(sm, 2, Xhi, Whi, row0, col0, 2 * BK, tid);
    cpa_commit();

    int stg = 0;
    for (int t = 0; t < NKT; t++) {
        if (t + 3 < NKT) cpa_wait<2>(); else cpa_wait<0>();
        __syncthreads();
        if (t + 3 < NKT) {
            gemm_prefetch(sm, (stg + 3) & 3, Xhi, Whi, row0, col0, (t + 3) * BK, tid);
            cpa_commit();
        }
        const uint32_t sb = smb + (uint32_t)stg * G_STAGE;
        const uint32_t aAh = sb + G_AHI + oA;
        const uint32_t aBh = sb + G_BHI + oB;

        #pragma unroll
        for (int kk = 0; kk < 2; kk++) {
            const uint32_t ko = kk * 32;
            uint32_t Ah[4][4];
            #pragma unroll
            for (int mt = 0; mt < 4; mt++)
                ldsm4(Ah[mt][0], Ah[mt][1], Ah[mt][2], Ah[mt][3], aAh + ko + mt * 16 * KSG * 2);
            #pragma unroll
            for (int p = 0; p < 2; p++) {
                uint32_t h0, h1, h2, h3;
                ldsm4(h0, h1, h2, h3, aBh + ko + p * 16 * KSG * 2);
                #pragma unroll
                for (int mt = 0; mt < 4; mt++) {
                    mma16816(acc[mt][2*p],   Ah[mt][0],Ah[mt][1],Ah[mt][2],Ah[mt][3], h0, h2);
                    mma16816(acc[mt][2*p+1], Ah[mt][0],Ah[mt][1],Ah[mt][2],Ah[mt][3], h1, h3);
                }
            }
        }
        stg = (stg + 1) & 3;
    }
}

// ---------------------------------------------------------------------------
// QKV projection: pure fp16 GEMM. Q pre-scaled by d^-0.5 * log2(e).
// ---------------------------------------------------------------------------
__global__ __launch_bounds__(256, 2) void qkv_gemm(
    const float* __restrict__ bq, const float* __restrict__ bk, const float* __restrict__ bv)
{
    extern __shared__ char sm[];
    const int z = blockIdx.z;
    const hf* Whi = g_whi[z];
    const float* bias = (z == 0) ? bq : (z == 1) ? bk : bv;
    const float scale = (z == 0) ? 0.125f * LOG2E : 1.0f;

    const int row0 = blockIdx.y * BM, col0 = blockIdx.x * BN;
    float acc[4][4][4] = {};
    gemm_core(sm, g_xhi, Whi, row0, col0, acc);

    const int lane = threadIdx.x & 31, wid = threadIdx.x >> 5;
    const int wm = (wid & 1) * 64, wn = (wid >> 1) * 32;
    const int g = lane >> 2, tg = lane & 3;

    #pragma unroll
    for (int mt = 0; mt < 4; mt++) {
        #pragma unroll
        for (int nt = 0; nt < 4; nt++) {
            const int c0 = col0 + wn + nt * 8 + tg * 2;
            const int h = c0 >> 6, d0 = c0 & 63;
            const float b0f = bias[c0], b1f = bias[c0 + 1];
            #pragma unroll
            for (int r = 0; r < 2; r++) {
                const int m = row0 + wm + mt * 16 + g + r * 8;
                const int b = m >> 10, n = m & 1023;
                float v0 = (acc[mt][nt][r * 2 + 0] + b0f) * scale;
                float v1 = (acc[mt][nt][r * 2 + 1] + b1f) * scale;
                if (z == 0) {
                    size_t base = ((size_t)(b * NH + h) * NSEQ + n) * DH + d0;
                    *(uint32_t*)&g_qhi[base] = pk2h(v0, v1);
                } else if (z == 1) {
                    size_t base = ((size_t)(b * NH + h) * NSEQ + n) * DH + d0;
                    *(uint32_t*)&g_khi[base] = pk2h(v0, v1);
                } else {
                    size_t vb = ((size_t)(b * NH + h) * DH + d0) * NSEQ + n;
                    g_vhi[vb]        = __float2half_rn(v0);
                    g_vhi[vb + NSEQ] = __float2half_rn(v1);
                }
            }
        }
    }
}

// ---------------------------------------------------------------------------
// Output projection: pure fp16 GEMM
// ---------------------------------------------------------------------------
__global__ __launch_bounds__(256, 2) void out_gemm(const float* __restrict__ bias,
                                                   float* __restrict__ out)
{
    extern __shared__ char sm[];
    const int row0 = blockIdx.y * BM, col0 = blockIdx.x * BN;
    float acc[4][4][4] = {};
    gemm_core(sm, g_ahi, g_whi[3], row0, col0, acc);

    const int lane = threadIdx.x & 31, wid = threadIdx.x >> 5;
    const int wm = (wid & 1) * 64, wn = (wid >> 1) * 32;
    const int g = lane >> 2, tg = lane & 3;

    #pragma unroll
    for (int mt = 0; mt < 4; mt++) {
        #pragma unroll
        for (int nt = 0; nt < 4; nt++) {
            const int c0 = col0 + wn + nt * 8 + tg * 2;
            const float b0f = bias[c0], b1f = bias[c0 + 1];
            #pragma unroll
            for (int r = 0; r < 2; r++) {
                const int m = row0 + wm + mt * 16 + g + r * 8;
                float2 v;
                v.x = acc[mt][nt][r * 2 + 0] + b0f;
                v.y = acc[mt][nt][r * 2 + 1] + b1f;
                *(float2*)(out + (size_t)m * EMB + c0) = v;
            }
        }
    }
}

// ---------------------------------------------------------------------------
// Tensor-core flash attention (R14 exact): fixed-shift softmax, all-hi fp16.
// CTA = 64 queries x one (b,h), 128 thr / 4 warps, kv tile 32, 4 CTAs/SM.
// Bias: software-pipelined register prefetch. K/V: cp.async 2-stage smem.
// ---------------------------------------------------------------------------
__global__ __launch_bounds__(128, 4) void attn_kernel(const float* __restrict__ bias)
{
    extern __shared__ char sm[];
    const int qb = blockIdx.x, bh = blockIdx.y;
    const int tid = threadIdx.x, lane = tid & 31, w = tid >> 5;
    const int g = lane >> 2, tg = lane & 3;
    const int wm = w * 16;
    const int qrow0 = qb * 64;

    // Q fragments, hi only (persistent in registers)
    uint32_t qh[4][4];
    {
        const hf* qbh = g_qhi + ((size_t)bh * NSEQ + qrow0 + wm) * DH;
        #pragma unroll
        for (int ks = 0; ks < 4; ks++) {
            const int kc = ks * 16 + tg * 2;
            qh[ks][0] = *(const uint32_t*)(qbh + g * DH + kc);
            qh[ks][1] = *(const uint32_t*)(qbh + (g + 8) * DH + kc);
            qh[ks][2] = *(const uint32_t*)(qbh + g * DH + kc + 8);
            qh[ks][3] = *(const uint32_t*)(qbh + (g + 8) * DH + kc + 8);
        }
    }

    float o[8][4] = {};
    float l0 = 0.0f, l1 = 0.0f;

    const hf* kph = g_khi + (size_t)bh * NSEQ * DH;
    const hf* vph = g_vhi + (size_t)bh * DH * NSEQ;
    const float* bp0 = bias + ((size_t)bh * NSEQ + qrow0 + wm + g) * NSEQ + tg * 2;
    const float* bp1 = bp0 + (size_t)8 * NSEQ;

    const int lrow = lane & 15, lc8 = (lane >> 4) * 8;
    const uint32_t smb = smem_u32(sm);
    const uint32_t oKm = (uint32_t)(lrow * KKS + lc8) * 2;
    const uint32_t oVm = (uint32_t)(lrow * VKS + lc8) * 2;

    auto prefetch = [&](int t, int buf) {
        char* base = sm + buf * A_STAGE;
        const int kv0 = t * 32;
        {
            const int r = tid >> 3, c = (tid & 7) * 8;
            #pragma unroll
            for (int ch = 0; ch < 2; ch++) {
                const int row = r + ch * 16;
                cpa16(smem_u32(base + A_KHI) + (uint32_t)(row * KKS + c) * 2,
                      kph + (size_t)(kv0 + row) * DH + c);
            }
        }
        {
            const int r = tid >> 2, c = (tid & 3) * 8;
            #pragma unroll
            for (int ch = 0; ch < 2; ch++) {
                const int row = r + ch * 32;
                cpa16(smem_u32(base + A_VHI) + (uint32_t)(row * VKS + c) * 2,
                      vph + (size_t)row * NSEQ + kv0 + c);
            }
        }
    };

    // bias register prefetch for tile 0
    float2 bc[8];
    #pragma unroll
    for (int nt = 0; nt < 4; nt++) {
        bc[nt]     = __ldcs((const float2*)(bp0 + nt * 8));
        bc[nt + 4] = __ldcs((const float2*)(bp1 + nt * 8));
    }

    prefetch(0, 0);
    cpa_commit();

    for (int t = 0; t < NSEQ / 32; t++) {
        cpa_wait<0>();
        __syncthreads();
        if (t + 1 < NSEQ / 32) { prefetch(t + 1, (t + 1) & 1); cpa_commit(); }
        const uint32_t sb = smb + (t & 1) * A_STAGE;
        const uint32_t aKh = sb + A_KHI + oKm;
        const uint32_t aVh = sb + A_VHI + oVm;

        // S init = bias*log2e - MSHIFT (consume bias regs)
        float s[4][4];
        #pragma unroll
        for (int nt = 0; nt < 4; nt++) {
            s[nt][0] = fmaf(bc[nt].x,     LOG2E, -MSHIFT);
            s[nt][1] = fmaf(bc[nt].y,     LOG2E, -MSHIFT);
            s[nt][2] = fmaf(bc[nt + 4].x, LOG2E, -MSHIFT);
            s[nt][3] = fmaf(bc[nt + 4].y, LOG2E, -MSHIFT);
        }

        // issue next tile's bias loads (latency hidden by MMA/exp below)
        if (t + 1 < NSEQ / 32) {
            const int kvn = (t + 1) * 32;
            #pragma unroll
            for (int nt = 0; nt < 4; nt++) {
                bc[nt]     = __ldcs((const float2*)(bp0 + kvn + nt * 8));
                bc[nt + 4] = __ldcs((const float2*)(bp1 + kvn + nt * 8));
            }
        }

        // S += Qhi Khi^T
        #pragma unroll
        for (int p = 0; p < 2; p++) {
            #pragma unroll
            for (int ks = 0; ks < 4; ks++) {
                uint32_t h0, h1, h2, h3;
                ldsm4(h0, h1, h2, h3, aKh + p * (16 * KKS * 2) + ks * 32);
                mma16816(s[2*p],   qh[ks][0],qh[ks][1],qh[ks][2],qh[ks][3], h0, h2);
                mma16816(s[2*p+1], qh[ks][0],qh[ks][1],qh[ks][2],qh[ks][3], h1, h3);
            }
        }

        // fixed-shift exp: p = 2^s; accumulate partial l
        #pragma unroll
        for (int nt = 0; nt < 4; nt++) {
            s[nt][0] = fexp2(s[nt][0]); l0 += s[nt][0];
            s[nt][1] = fexp2(s[nt][1]); l0 += s[nt][1];
            s[nt][2] = fexp2(s[nt][2]); l1 += s[nt][2];
            s[nt][3] = fexp2(s[nt][3]); l1 += s[nt][3];
        }

        // pack P (hi only) into PV A-fragments
        uint32_t ph[2][4];
        #pragma unroll
        for (int j = 0; j < 2; j++) {
            ph[j][0] = pk2h(s[2*j][0],   s[2*j][1]);
            ph[j][1] = pk2h(s[2*j][2],   s[2*j][3]);
            ph[j][2] = pk2h(s[2*j+1][0], s[2*j+1][1]);
            ph[j][3] = pk2h(s[2*j+1][2], s[2*j+1][3]);
        }

        // O += Phi Vhi
        #pragma unroll
        for (int p = 0; p < 4; p++) {
            #pragma unroll
            for (int j = 0; j < 2; j++) {
                uint32_t h0, h1, h2, h3;
                ldsm4(h0, h1, h2, h3, aVh + p * (16 * VKS * 2) + j * 32);
                mma16816(o[2*p],   ph[j][0],ph[j][1],ph[j][2],ph[j][3], h0, h2);
                mma16816(o[2*p+1], ph[j][0],ph[j][1],ph[j][2],ph[j][3], h1, h3);
            }
        }
    }

    // final l reduction across the 4 tg lanes of each row
    l0 += __shfl_xor_sync(0xffffffffu, l0, 1);
    l0 += __shfl_xor_sync(0xffffffffu, l0, 2);
    l1 += __shfl_xor_sync(0xffffffffu, l1, 1);
    l1 += __shfl_xor_sync(0xffffffffu, l1, 2);

    // epilogue: normalize, pack hi-only fp16, store into (b,n,e)
    const float inv0 = 1.0f / l0, inv1 = 1.0f / l1;
    const int b = bh / NH, h = bh % NH;
    const int n0 = qrow0 + wm + g;
    const size_t base0 = ((size_t)b * NSEQ + n0) * EMB + h * DH;
    const size_t base1 = base0 + (size_t)8 * EMB;
    #pragma unroll
    for (int dn = 0; dn < 8; dn++) {
        const int d = dn * 8 + tg * 2;
        *(uint32_t*)&g_ahi[base0 + d] = pk2h(o[dn][0] * inv0, o[dn][1] * inv0);
        *(uint32_t*)&g_ahi[base1 + d] = pk2h(o[dn][2] * inv1, o[dn][3] * inv1);
    }
}

// ---------------------------------------------------------------------------
extern "C" void kernel_launch(void* const* d_in, const int* in_sizes, int n_in,
                              void* d_out, int out_size)
{
    const float* query     = (const float*)d_in[0];
    const float* attn_bias = (const float*)d_in[1];
    const float* Wq = (const float*)d_in[2];
    const float* bq = (const float*)d_in[3];
    const float* Wk = (const float*)d_in[4];
    const float* bk = (const float*)d_in[5];
    const float* Wv = (const float*)d_in[6];
    const float* bv = (const float*)d_in[7];
    const float* Wo = (const float*)d_in[8];
    const float* bo = (const float*)d_in[9];
    float* out = (float*)d_out;

    cudaFuncSetAttribute(qkv_gemm,    cudaFuncAttributeMaxDynamicSharedMemorySize, G_SMEM);
    cudaFuncSetAttribute(out_gemm,    cudaFuncAttributeMaxDynamicSharedMemorySize, G_SMEM);
    cudaFuncSetAttribute(attn_kernel, cudaFuncAttributeMaxDynamicSharedMemorySize, A_SMEM);

    conv_x<<<(MTOK * EMB / 8 + 255) / 256, 256>>>(query);
    dim3 gw((EMB * EMB / 8 + 255) / 256, 4);
    conv_w4<<<gw, 256>>>(Wq, Wk, Wv, Wo);

    dim3 g1(EMB / BN, MTOK / BM, 3);
    qkv_gemm<<<g1, 256, G_SMEM>>>(bq, bk, bv);

    dim3 g2(NSEQ / 64, BSZ * NH);
    attn_kernel<<<g2, 128, A_SMEM>>>(attn_bias);

    dim3 g3(EMB / BN, MTOK / BM);
    out_gemm<<<g3, 256, G_SMEM>>>(bo, out);
}